// round 17
// baseline (speedup 1.0000x reference)
#include <cuda_runtime.h>
#include <math.h>

#define HIDDEN 1024
#define HEADS  8
#define HEAD   128
#define BATCH  512

__device__ __forceinline__ float dot4(float4 a, float4 b) {
    return a.x*b.x + a.y*b.y + a.z*b.z + a.w*b.w;
}

// 16-byte async copy to shared (L2-only): register-free prefetch.
__device__ __forceinline__ void cp_async16(void* dst_smem, const float* src) {
    unsigned int d = (unsigned int)__cvta_generic_to_shared(dst_smem);
    asm volatile("cp.async.cg.shared.global [%0], [%1], 16;" :: "r"(d), "l"(src));
}

// ---------------------------------------------------------------------------
// Fully fused gate GEMV + mLSTM step + GroupNorm.
// One (b,h) tile per block, 512 threads, 2 CTAs/SM.
// FULL-TILE REGISTER FRONT-LOAD: each thread owns 8 float4 of the 128x128
// tile, all 8 LDG.128 issued at kernel ENTRY -> the entire tile is in flight
// before the gate GEMV; the main loop has ZERO loads (pure FMA + STG).
// Per-SM in-flight bytes and warp count identical to the 256-thread champion
// (128KB, 32 warps); only the load schedule and barrier scope change.
// Gate GEMV split: threads <256 do q+v dots, threads >=256 do k dots.
// ---------------------------------------------------------------------------
__global__ __launch_bounds__(512, 2) void mlstm_fused_kernel(
    const float* __restrict__ q, const float* __restrict__ k,
    const float* __restrict__ v, const float* __restrict__ cell,
    const float* __restrict__ norm, const float* __restrict__ maxs,
    const float* __restrict__ Wi, const float* __restrict__ bi,
    const float* __restrict__ Wf, const float* __restrict__ bf,
    const float* __restrict__ gamma, const float* __restrict__ beta,
    float* __restrict__ out, float* __restrict__ cell_out,
    float* __restrict__ norm_out, float* __restrict__ max_out)
{
    int bh   = blockIdx.x;
    int b    = bh >> 3;
    int h    = bh & 7;
    int tid  = threadIdx.x;          // 0..511
    int lane = tid & 31;
    int warp = tid >> 5;             // 0..15

    __shared__ __align__(16) float q_s[HEAD];
    __shared__ __align__(16) float k_s[HEAD];
    __shared__ __align__(16) float v_s[HEAD];
    __shared__ __align__(16) float norm_s[HEAD];
    __shared__ float4 snum[512];
    __shared__ float pig[16], pfg[16], pq[4];
    __shared__ float s_mu, s_rstd;

    const float rsqrtD = 0.08838834764831845f;  // 1/sqrt(128)

    // ---- cell tile: warp = row-in-group (16 rows/iter), lane = f4 column ---
    const float4* cp = (const float4*)(cell + (size_t)bh * HEAD * HEAD)
                       + warp * 32 + lane;
    float4* op = cell_out
               ? (float4*)(cell_out + (size_t)bh * HEAD * HEAD) + warp * 32 + lane
               : (float4*)0;

    // ---- ENTRY: issue the ENTIRE tile's loads (8 per thread) ---------------
    float4 cv[8];
    #pragma unroll
    for (int i = 0; i < 8; ++i)
        cv[i] = __ldcs(cp + i * 512);            // row i*16 + warp

    if (tid < 32) {       // norm row -> smem, register-free
        cp_async16(&norm_s[tid * 4], norm + (size_t)bh * HEAD + tid * 4);
        asm volatile("cp.async.commit_group;" ::: "memory");
    }
    float m_old = maxs[bh];                      // block-uniform scalars
    float bih   = bi[h];
    float bfh   = bf[h];

    // ---- gate pre-activations: igp/fgp = qkv_row . W[h] + b[h] -------------
    const float4* qrow = (const float4*)(q + (size_t)b * HIDDEN);
    const float4* krow = (const float4*)(k + (size_t)b * HIDDEN);
    const float4* vrow = (const float4*)(v + (size_t)b * HIDDEN);
    const float4* Wi4  = (const float4*)Wi + (size_t)h * 768;
    const float4* Wf4  = (const float4*)Wf + (size_t)h * 768;

    float ai = 0.f, af = 0.f;
    if (tid < 256) {                 // q (and v) partial dots
        float4 x0 = qrow[tid];
        float4 x1 = vrow[tid];
        ai = dot4(x0, Wi4[tid]) + dot4(x1, Wi4[512 + tid]);
        af = dot4(x0, Wf4[tid]) + dot4(x1, Wf4[512 + tid]);
        if (warp == h) {             // head slice lives here: stash q and v
            ((float4*)q_s)[lane] = x0;
            ((float4*)v_s)[lane] = x1;
        }
    } else {                         // k partial dots
        int t = tid - 256;
        float4 x0 = krow[t];
        ai = dot4(x0, Wi4[256 + t]);
        af = dot4(x0, Wf4[256 + t]);
        if (warp == 8 + h) {         // head k slice: stash scaled
            float4 sk;
            sk.x = x0.x * rsqrtD; sk.y = x0.y * rsqrtD;
            sk.z = x0.z * rsqrtD; sk.w = x0.w * rsqrtD;
            ((float4*)k_s)[lane] = sk;
        }
    }

    #pragma unroll
    for (int off = 16; off > 0; off >>= 1) {
        ai += __shfl_xor_sync(0xffffffffu, ai, off);
        af += __shfl_xor_sync(0xffffffffu, af, off);
    }
    if (lane == 0) { pig[warp] = ai; pfg[warp] = af; }
    if (tid < 32)   // norm row must be in smem before sync publishes it
        asm volatile("cp.async.wait_group 0;" ::: "memory");
    __syncthreads();                                   // sync #1

    float igp = bih, fgp = bfh;
    #pragma unroll
    for (int w = 0; w < 16; ++w) { igp += pig[w]; fgp += pfg[w]; }

    float log_f = fminf(fgp, 0.f) - log1pf(expf(-fabsf(fgp)));   // log sigmoid
    float m_new = fmaxf(igp, m_old + log_f);
    float i_g   = expf(igp - m_new);
    float f_g   = expf(log_f + m_old - m_new);

    if (tid == 0 && max_out) max_out[bh] = m_new;

    // ---- norm update + qn partials (norm_s already resident) ---------------
    if (tid < HEAD) {
        float nn = fmaf(f_g, norm_s[tid], i_g * k_s[tid]);
        if (norm_out) norm_out[(size_t)bh * HEAD + tid] = nn;
        float qn = q_s[tid] * nn;
        #pragma unroll
        for (int off = 16; off > 0; off >>= 1)
            qn += __shfl_xor_sync(0xffffffffu, qn, off);
        if (lane == 0) pq[warp] = qn;
    }

    // ---- main loop: 8 iterations of 16 rows, ZERO loads (all resident) ------
    float4 vreg = ((const float4*)v_s)[lane];
    float4 num  = make_float4(0.f, 0.f, 0.f, 0.f);

    #pragma unroll
    for (int i = 0; i < 8; ++i) {
        float4 c = cv[i];
        int r = i * 16 + warp;
        float a = i_g * k_s[r];
        float4 cn;
        cn.x = fmaf(f_g, c.x, a * vreg.x);
        cn.y = fmaf(f_g, c.y, a * vreg.y);
        cn.z = fmaf(f_g, c.z, a * vreg.z);
        cn.w = fmaf(f_g, c.w, a * vreg.w);
        if (op) __stcs(op + i * 512, cn);
        float qr = q_s[r];
        num.x = fmaf(qr, cn.x, num.x);
        num.y = fmaf(qr, cn.y, num.y);
        num.z = fmaf(qr, cn.z, num.z);
        num.w = fmaf(qr, cn.w, num.w);
    }

    // ---- numerator reduction + denominator + GN stats, all in warp 0 --------
    snum[tid] = num;
    __syncthreads();                                   // sync #2 (covers pq)
    if (tid < 32) {
        float4 a = snum[tid];
        #pragma unroll
        for (int j = 1; j < 16; ++j) {
            float4 bb = snum[tid + 32 * j];
            a.x += bb.x; a.y += bb.y; a.z += bb.z; a.w += bb.w;
        }
        float qn    = pq[0] + pq[1] + pq[2] + pq[3];
        float denom = fmaxf(fabsf(qn), expf(-m_new)) + 1e-6f;
        float inv   = 1.f / denom;
        a.x *= inv; a.y *= inv; a.z *= inv; a.w *= inv;
        snum[tid] = a;                 // flattened: o[0..127]
        float so  = a.x + a.y + a.z + a.w;
        float so2 = a.x*a.x + a.y*a.y + a.z*a.z + a.w*a.w;
        #pragma unroll
        for (int off = 16; off > 0; off >>= 1) {
            so  += __shfl_xor_sync(0xffffffffu, so,  off);
            so2 += __shfl_xor_sync(0xffffffffu, so2, off);
        }
        if (lane == 0) {
            float mu  = so * (1.f / HEAD);
            float var = so2 * (1.f / HEAD) - mu * mu;
            s_mu   = mu;
            s_rstd = rsqrtf(var + 1e-5f);
        }
    }
    __syncthreads();                                   // sync #3

    if (tid < HEAD) {
        float o  = ((const float*)snum)[tid];
        int   ch = h * HEAD + tid;
        out[(size_t)b * HIDDEN + ch] = (o - s_mu) * s_rstd * gamma[ch] + beta[ch];
    }
}

// ---------------------------------------------------------------------------
extern "C" void kernel_launch(void* const* d_in, const int* in_sizes, int n_in,
                              void* d_out, int out_size)
{
    const float* q     = (const float*)d_in[0];
    const float* k     = (const float*)d_in[1];
    const float* v     = (const float*)d_in[2];
    const float* cell  = (const float*)d_in[3];
    const float* norm  = (const float*)d_in[4];
    const float* maxs  = (const float*)d_in[5];
    const float* Wi    = (const float*)d_in[6];
    const float* bi    = (const float*)d_in[7];
    const float* Wf    = (const float*)d_in[8];
    const float* bf    = (const float*)d_in[9];
    const float* gamma = (const float*)d_in[10];
    const float* beta  = (const float*)d_in[11];

    float* out = (float*)d_out;

    const size_t OUT_N  = (size_t)BATCH * HIDDEN;                 // 524288
    const size_t CELL_N = (size_t)BATCH * HEADS * HEAD * HEAD;    // 67108864
    const size_t NORM_N = (size_t)BATCH * HEADS * HEAD;           // 524288
    const size_t MAX_N  = (size_t)BATCH * HEADS;                  // 4096

    float* cell_out = 0;
    float* norm_out = 0;
    float* max_out  = 0;
    if ((size_t)out_size >= OUT_N + CELL_N + NORM_N + MAX_N) {
        cell_out = out + OUT_N;
        norm_out = cell_out + CELL_N;
        max_out  = norm_out + NORM_N;
    }

    mlstm_fused_kernel<<<BATCH * HEADS, 512>>>(q, k, v, cell, norm, maxs,
                                               Wi, bi, Wf, bf, gamma, beta,
                                               out, cell_out, norm_out, max_out);
}